// round 2
// baseline (speedup 1.0000x reference)
#include <cuda_runtime.h>
#include <cuda_bf16.h>

#define NN 400000
#define EE 3200000
#define HH 100
#define NB_SCAN 391   // ceil(NN/1024)

typedef unsigned long long u64;

// ---------------- scratch (static device memory; no allocations) ------------
__device__ int   g_is64;
__device__ int   g_outdeg[NN];
__device__ int   g_indeg[NN];
__device__ int   g_rowptr[NN + 1];
__device__ int   g_blocksums[NB_SCAN];
__device__ int   g_blockoff[NB_SCAN];
__device__ int   g_cursor[NN];
__device__ float g_dinv[NN];
__device__ int   g_csrsrc[EE];
__device__ float g_csrw[EE];

__device__ float g_h [NN * HH];
__device__ float g_t1[NN * HH];
__device__ float g_t2[NN * HH];
__device__ float g_t3[NN * HH];
__device__ float g_t4[NN * HH];
__device__ float g_z [NN * HH];

__device__ float g_s1[NN * 2];
__device__ float g_s2[NN * 2];
__device__ float g_s3[NN * 2];
__device__ float g_s4[NN * 2];

__device__ float g_colsum[HH];
__device__ float g_colsq [HH];
__device__ float g_bna[HH];
__device__ float g_bnb[HH];

// ---------------- f32x2 helpers (FFMA2 — only reachable via PTX) ------------
__device__ __forceinline__ u64 ffma2(u64 a, u64 b, u64 c) {
    u64 d;
    asm("fma.rn.f32x2 %0, %1, %2, %3;" : "=l"(d) : "l"(a), "l"(b), "l"(c));
    return d;
}
__device__ __forceinline__ u64 pack2(float lo, float hi) {
    u64 d;
    asm("mov.b64 %0, {%1, %2};" : "=l"(d) : "f"(lo), "f"(hi));
    return d;
}
__device__ __forceinline__ void unpack2(u64 d, float& lo, float& hi) {
    asm("mov.b64 {%0, %1}, %2;" : "=f"(lo), "=f"(hi) : "l"(d));
}

// ---------------- edge dtype detection --------------------------------------
// jax.random.randint(dtype=int64) silently yields int32 when x64 is disabled.
// Real int64 node-ids are all < 400000 (high word 0). int32 data misread as
// int64 has the *next* edge value in the high word -> >= 2^32 almost surely.
__global__ void k_detect(const void* __restrict__ ei) {
    const long long* p = (const long long*)ei;
    int is64 = 1;
    for (int i = 0; i < 256; i++) {
        long long v = p[i];
        if (v < 0 || v >= NN) { is64 = 0; break; }
    }
    g_is64 = is64;
}

__device__ __forceinline__ void load_edge(const void* __restrict__ ei, int e,
                                          int& s, int& d) {
    if (g_is64) {
        const long long* p = (const long long*)ei;
        s = (int)p[e];
        d = (int)p[EE + e];
    } else {
        const int* p = (const int*)ei;
        s = p[e];
        d = p[EE + e];
    }
}

// ---------------- preprocessing ---------------------------------------------
__global__ void k_zero_pre() {
    int i = blockIdx.x * blockDim.x + threadIdx.x;
    if (i < NN) { g_outdeg[i] = 0; g_indeg[i] = 0; g_cursor[i] = 0; }
}

__global__ void k_hist(const void* __restrict__ ei) {
    int e = blockIdx.x * blockDim.x + threadIdx.x;
    if (e < EE) {
        int s, d;
        load_edge(ei, e, s, d);
        atomicAdd(&g_outdeg[s], 1);
        atomicAdd(&g_indeg[d], 1);
    }
}

__global__ void k_dinv() {
    int i = blockIdx.x * blockDim.x + threadIdx.x;
    if (i < NN) {
        int d = g_outdeg[i];
        g_dinv[i] = (d > 0) ? rsqrtf((float)d) : 0.0f;
    }
}

__global__ void k_scan1() {
    __shared__ int sm[1024];
    int t = threadIdx.x;
    int i = blockIdx.x * 1024 + t;
    int v = (i < NN) ? g_indeg[i] : 0;
    sm[t] = v;
    __syncthreads();
    for (int off = 1; off < 1024; off <<= 1) {
        int x = (t >= off) ? sm[t - off] : 0;
        __syncthreads();
        sm[t] += x;
        __syncthreads();
    }
    if (i < NN) g_rowptr[i] = sm[t] - v;       // exclusive within block
    if (t == 1023) g_blocksums[blockIdx.x] = sm[t];
}

__global__ void k_scan2() {
    __shared__ int sm[512];
    int t = threadIdx.x;
    int v = (t < NB_SCAN) ? g_blocksums[t] : 0;
    sm[t] = v;
    __syncthreads();
    for (int off = 1; off < 512; off <<= 1) {
        int x = (t >= off) ? sm[t - off] : 0;
        __syncthreads();
        sm[t] += x;
        __syncthreads();
    }
    if (t < NB_SCAN) g_blockoff[t] = sm[t] - v; // exclusive
}

__global__ void k_scan3() {
    int i = blockIdx.x * blockDim.x + threadIdx.x;
    if (i < NN) g_rowptr[i] += g_blockoff[i >> 10];
    if (i == 0) g_rowptr[NN] = EE;
}

__global__ void k_scatter(const void* __restrict__ ei) {
    int e = blockIdx.x * blockDim.x + threadIdx.x;
    if (e < EE) {
        int s, d;
        load_edge(ei, e, s, d);
        int pos = g_rowptr[d] + atomicAdd(&g_cursor[d], 1);
        g_csrsrc[pos] = s;
        g_csrw[pos]   = -g_dinv[s] * g_dinv[d];
    }
}

// ---------------- layer-0 propagation (width 2) ------------------------------
__global__ void k_prop2(const float* __restrict__ in, const float* __restrict__ sub,
                        float* __restrict__ out, float alpha, float beta) {
    int i = blockIdx.x * blockDim.x + threadIdx.x;
    if (i >= NN) return;
    int p0 = g_rowptr[i], p1 = g_rowptr[i + 1];
    float a0 = 0.f, a1 = 0.f;
    for (int p = p0; p < p1; p++) {
        int s = g_csrsrc[p];
        float w = g_csrw[p];
        a0 += w * in[2 * s];
        a1 += w * in[2 * s + 1];
    }
    if (beta != 0.f) {
        out[2 * i]     = alpha * a0 + beta * sub[2 * i];
        out[2 * i + 1] = alpha * a1 + beta * sub[2 * i + 1];
    } else {
        out[2 * i]     = alpha * a0;
        out[2 * i + 1] = alpha * a1;
    }
}

// ---------------- layer-0 GEMM: [N,2]x5 -> [N,100], +bias, relu --------------
__global__ void k_gemm0(const float* __restrict__ x,  const float* __restrict__ s1,
                        const float* __restrict__ s2, const float* __restrict__ s3,
                        const float* __restrict__ s4, const float* __restrict__ W0,
                        const float* __restrict__ b0, float* __restrict__ Z) {
    __shared__ float sw[1000];
    __shared__ float sb[HH];
    int tid = threadIdx.y * 32 + threadIdx.x;
    for (int i = tid; i < 1000; i += 256) sw[i] = W0[i];
    for (int i = tid; i < HH; i += 256) sb[i] = b0[i];
    __syncthreads();

    int n = blockIdx.x * 8 + threadIdx.y;
    float v[10];
    v[0] = x[2 * n]; v[1] = x[2 * n + 1];
    v[2] = s1[2 * n]; v[3] = s1[2 * n + 1];
    v[4] = s2[2 * n]; v[5] = s2[2 * n + 1];
    v[6] = s3[2 * n]; v[7] = s3[2 * n + 1];
    v[8] = s4[2 * n]; v[9] = s4[2 * n + 1];

    #pragma unroll
    for (int j = 0; j < 4; j++) {
        int c = threadIdx.x + 32 * j;
        if (c < HH) {
            float acc = sb[c];
            #pragma unroll
            for (int k = 0; k < 5; k++) {
                acc += v[2 * k]     * sw[(2 * k) * HH + c];
                acc += v[2 * k + 1] * sw[(2 * k + 1) * HH + c];
            }
            Z[n * HH + c] = fmaxf(acc, 0.0f);
        }
    }
}

// ---------------- width-100 propagation: warp per dst row --------------------
__global__ void __launch_bounds__(256) k_prop100(
    const float* __restrict__ in, const float* __restrict__ sub,
    float* __restrict__ out, float alpha, float beta) {
    int warp = (blockIdx.x * blockDim.x + threadIdx.x) >> 5;
    int lane = threadIdx.x & 31;
    if (warp >= NN) return;
    int p0 = g_rowptr[warp], p1 = g_rowptr[warp + 1];
    float a0 = 0.f, a1 = 0.f, a2 = 0.f, a3 = 0.f;
    for (int p = p0; p < p1; p++) {
        int s = g_csrsrc[p];
        float w = g_csrw[p];
        const float* r = in + (size_t)s * HH;
        a0 += w * r[lane];
        a1 += w * r[lane + 32];
        a2 += w * r[lane + 64];
        if (lane < 4) a3 += w * r[lane + 96];
    }
    float* o = out + (size_t)warp * HH;
    if (beta != 0.f) {
        const float* sb = sub + (size_t)warp * HH;
        o[lane]      = alpha * a0 + beta * sb[lane];
        o[lane + 32] = alpha * a1 + beta * sb[lane + 32];
        o[lane + 64] = alpha * a2 + beta * sb[lane + 64];
        if (lane < 4) o[lane + 96] = alpha * a3 + beta * sb[lane + 96];
    } else {
        o[lane]      = alpha * a0;
        o[lane + 32] = alpha * a1;
        o[lane + 64] = alpha * a2;
        if (lane < 4) o[lane + 96] = alpha * a3;
    }
}

// ---------------- main GEMM: Z = relu([T0..T4]@Wcat + b) ---------------------
// C[400000,100] = A[400000,500] * W[500,100];  A = 5 buffers of [N,100].
// Block: 256 thr (16x16), tile 128 rows x 128 cols (100 valid), KC=20 (never
// crosses a 100-col buffer boundary since 100 % 20 == 0).
__global__ void __launch_bounds__(256) k_gemm100(
    const float* __restrict__ t0, const float* __restrict__ t1,
    const float* __restrict__ t2, const float* __restrict__ t3,
    const float* __restrict__ t4,
    const float* __restrict__ W, const float* __restrict__ bias,
    float* __restrict__ Z) {
    __shared__ float sA[20][128];
    __shared__ float sW[20][128];

    const float* bufs[5] = { t0, t1, t2, t3, t4 };

    int tc = threadIdx.x;            // 0..15
    int tr = threadIdx.y;            // 0..15
    int tid = tr * 16 + tc;
    int rowbase = blockIdx.x * 128;

    u64 acc[8][4];
    #pragma unroll
    for (int j = 0; j < 8; j++)
        #pragma unroll
        for (int m = 0; m < 4; m++) acc[j][m] = 0ull;

    for (int ch = 0; ch < 25; ch++) {
        int kc0 = ch * 20;
        const float* A = bufs[kc0 / 100];
        int col0 = kc0 % 100;

        // stage A: 128 rows x 20 k (transposed into sA[k][row])
        {
            int r = tid >> 1;
            int half = tid & 1;
            const float* src = A + (size_t)(rowbase + r) * HH + col0 + half * 10;
            #pragma unroll
            for (int i = 0; i < 10; i++) sA[half * 10 + i][r] = src[i];
        }
        // stage W: 20 x 128 (cols >= 100 zero-padded)
        {
            #pragma unroll
            for (int i = 0; i < 10; i++) {
                int lin = tid * 10 + i;          // 0..2559
                int kk = lin >> 7;
                int c  = lin & 127;
                sW[kk][c] = (c < HH) ? W[(kc0 + kk) * HH + c] : 0.0f;
            }
        }
        __syncthreads();

        #pragma unroll
        for (int kk = 0; kk < 20; kk++) {
            float4 av0 = *(const float4*)&sA[kk][tr * 8];
            float4 av1 = *(const float4*)&sA[kk][tr * 8 + 4];
            float4 wv0 = *(const float4*)&sW[kk][tc * 8];
            float4 wv1 = *(const float4*)&sW[kk][tc * 8 + 4];
            u64 wp[4];
            wp[0] = pack2(wv0.x, wv0.y);
            wp[1] = pack2(wv0.z, wv0.w);
            wp[2] = pack2(wv1.x, wv1.y);
            wp[3] = pack2(wv1.z, wv1.w);
            float ar[8] = { av0.x, av0.y, av0.z, av0.w, av1.x, av1.y, av1.z, av1.w };
            #pragma unroll
            for (int j = 0; j < 8; j++) {
                u64 ab = pack2(ar[j], ar[j]);
                #pragma unroll
                for (int m = 0; m < 4; m++) acc[j][m] = ffma2(ab, wp[m], acc[j][m]);
            }
        }
        __syncthreads();
    }

    // epilogue: + bias, relu, masked store (cols >= 100 discarded)
    int c0 = tc * 8;
    if (c0 >= HH) return;
    float bv[8];
    #pragma unroll
    for (int m = 0; m < 8; m++) bv[m] = (c0 + m < HH) ? bias[c0 + m] : 0.0f;

    #pragma unroll
    for (int j = 0; j < 8; j++) {
        int r = rowbase + tr * 8 + j;
        float res[8];
        #pragma unroll
        for (int m = 0; m < 4; m++) unpack2(acc[j][m], res[2 * m], res[2 * m + 1]);
        #pragma unroll
        for (int m = 0; m < 8; m++) res[m] = fmaxf(res[m] + bv[m], 0.0f);
        float* zr = Z + (size_t)r * HH + c0;
        if (c0 + 8 <= HH) {
            *(float4*)zr       = make_float4(res[0], res[1], res[2], res[3]);
            *(float4*)(zr + 4) = make_float4(res[4], res[5], res[6], res[7]);
        } else {  // c0 == 96
            *(float4*)zr = make_float4(res[0], res[1], res[2], res[3]);
        }
    }
}

// ---------------- batch-norm ------------------------------------------------
__global__ void k_zero_bn() {
    int i = threadIdx.x;
    if (i < HH) { g_colsum[i] = 0.f; g_colsq[i] = 0.f; }
}

__global__ void k_stats(const float* __restrict__ Z) {
    int tx = threadIdx.x, ty = threadIdx.y;
    int r0 = blockIdx.x * 1000;
    float s[4] = {0, 0, 0, 0}, q[4] = {0, 0, 0, 0};
    for (int r = r0 + ty; r < r0 + 1000; r += 8) {
        const float* zr = Z + (size_t)r * HH;
        #pragma unroll
        for (int j = 0; j < 4; j++) {
            int c = tx + 32 * j;
            if (c < HH) {
                float v = zr[c];
                s[j] += v;
                q[j] += v * v;
            }
        }
    }
    #pragma unroll
    for (int j = 0; j < 4; j++) {
        int c = tx + 32 * j;
        if (c < HH) {
            atomicAdd(&g_colsum[c], s[j]);
            atomicAdd(&g_colsq[c], q[j]);
        }
    }
}

__global__ void k_bnfinal(const float* __restrict__ gamma, const float* __restrict__ beta) {
    int c = threadIdx.x;
    if (c < HH) {
        float m = g_colsum[c] * (1.0f / NN);
        float v = g_colsq[c] * (1.0f / NN) - m * m;
        float a = gamma[c] * rsqrtf(v + 1e-5f);
        g_bna[c] = a;
        g_bnb[c] = beta[c] - a * m;
    }
}

__global__ void k_norm(const float* __restrict__ Z, float* __restrict__ out) {
    int i = blockIdx.x * blockDim.x + threadIdx.x;
    if (i >= NN * HH / 4) return;
    float4 z = ((const float4*)Z)[i];
    int c0 = (i % 25) * 4;
    float4 r;
    r.x = g_bna[c0]     * z.x + g_bnb[c0];
    r.y = g_bna[c0 + 1] * z.y + g_bnb[c0 + 1];
    r.z = g_bna[c0 + 2] * z.z + g_bnb[c0 + 2];
    r.w = g_bna[c0 + 3] * z.w + g_bnb[c0 + 3];
    ((float4*)out)[i] = r;
}

// ---------------- host ------------------------------------------------------
extern "C" void kernel_launch(void* const* d_in, const int* in_sizes, int n_in,
                              void* d_out, int out_size) {
    const float* x     = (const float*)d_in[0];
    const void*  ei    = d_in[1];          // int32 or int64 — detected on device
    const float* W0    = (const float*)d_in[2];
    const float* b0    = (const float*)d_in[3];
    const float* Wr    = (const float*)d_in[4];
    const float* br    = (const float*)d_in[5];
    const float* gamma = (const float*)d_in[6];
    const float* beta  = (const float*)d_in[7];
    float* out = (float*)d_out;

    float *h, *t1, *t2, *t3, *t4, *z, *s1, *s2, *s3, *s4;
    cudaGetSymbolAddress((void**)&h,  g_h);
    cudaGetSymbolAddress((void**)&t1, g_t1);
    cudaGetSymbolAddress((void**)&t2, g_t2);
    cudaGetSymbolAddress((void**)&t3, g_t3);
    cudaGetSymbolAddress((void**)&t4, g_t4);
    cudaGetSymbolAddress((void**)&z,  g_z);
    cudaGetSymbolAddress((void**)&s1, g_s1);
    cudaGetSymbolAddress((void**)&s2, g_s2);
    cudaGetSymbolAddress((void**)&s3, g_s3);
    cudaGetSymbolAddress((void**)&s4, g_s4);

    const int TB = 256;
    const int gN = (NN + TB - 1) / TB;   // 1563
    const int gE = (EE + TB - 1) / TB;   // 12500

    // ---- CSR preprocessing (dst-sorted, atomic-free props afterwards) ----
    k_detect<<<1, 1>>>(ei);
    k_zero_pre<<<gN, TB>>>();
    k_hist<<<gE, TB>>>(ei);
    k_dinv<<<gN, TB>>>();
    k_scan1<<<NB_SCAN, 1024>>>();
    k_scan2<<<1, 512>>>();
    k_scan3<<<gN, TB>>>();
    k_scatter<<<gE, TB>>>(ei);

    // ---- layer 0 (width F_IN=2) ----
    k_prop2<<<gN, TB>>>(x,  x,  s1, 1.f,  0.f);
    k_prop2<<<gN, TB>>>(s1, x,  s2, 2.f, -1.f);
    k_prop2<<<gN, TB>>>(s2, s1, s3, 2.f, -1.f);
    k_prop2<<<gN, TB>>>(s3, s2, s4, 2.f, -1.f);
    k_gemm0<<<NN / 8, dim3(32, 8)>>>(x, s1, s2, s3, s4, W0, b0, z);
    k_zero_bn<<<1, 128>>>();
    k_stats<<<400, dim3(32, 8)>>>(z);
    k_bnfinal<<<1, 128>>>(gamma, beta);
    k_norm<<<(NN * HH / 4 + TB - 1) / TB, TB>>>(z, h);

    // ---- layers 1..4 (width 100) ----
    for (int l = 1; l < 5; l++) {
        k_prop100<<<NN / 8, TB>>>(h,  h,  t1, 1.f,  0.f);
        k_prop100<<<NN / 8, TB>>>(t1, h,  t2, 2.f, -1.f);
        k_prop100<<<NN / 8, TB>>>(t2, t1, t3, 2.f, -1.f);
        k_prop100<<<NN / 8, TB>>>(t3, t2, t4, 2.f, -1.f);
        k_gemm100<<<NN / 128, dim3(16, 16)>>>(h, t1, t2, t3, t4,
                                              Wr + (l - 1) * 5 * HH * HH,
                                              br + (l - 1) * HH, z);
        k_zero_bn<<<1, 128>>>();
        k_stats<<<400, dim3(32, 8)>>>(z);
        k_bnfinal<<<1, 128>>>(gamma + l * HH, beta + l * HH);
        k_norm<<<(NN * HH / 4 + TB - 1) / TB, TB>>>(z, (l == 4) ? out : h);
    }
}

// round 4
// speedup vs baseline: 1.2001x; 1.2001x over previous
#include <cuda_runtime.h>
#include <cuda_bf16.h>
#include <cstdint>

#define NN 400000
#define EE 3200000
#define HH 100
#define NB_SCAN 391   // ceil(NN/1024)

typedef unsigned long long u64;

// ---------------- scratch (static device memory; no allocations) ------------
__device__ int   g_is64;
__device__ int   g_outdeg[NN];
__device__ int   g_indeg[NN];
__device__ int   g_rowptr[NN + 1];
__device__ int   g_blocksums[NB_SCAN];
__device__ int   g_blockoff[NB_SCAN];
__device__ int   g_cursor[NN];
__device__ float g_dinv[NN];
__device__ int   g_csrsrc[EE];
__device__ float g_csrw[EE];

__device__ float g_h [NN * HH];
__device__ float g_t1[NN * HH];
__device__ float g_t2[NN * HH];
__device__ float g_t3[NN * HH];
__device__ float g_t4[NN * HH];
__device__ float g_z [NN * HH];

__device__ float g_s1[NN * 2];
__device__ float g_s2[NN * 2];
__device__ float g_s3[NN * 2];
__device__ float g_s4[NN * 2];

__device__ float g_colsum[HH];
__device__ float g_colsq [HH];
__device__ float g_bna[HH];
__device__ float g_bnb[HH];

// ---------------- edge dtype detection --------------------------------------
__global__ void k_detect(const void* __restrict__ ei) {
    const long long* p = (const long long*)ei;
    int is64 = 1;
    for (int i = 0; i < 256; i++) {
        long long v = p[i];
        if (v < 0 || v >= NN) { is64 = 0; break; }
    }
    g_is64 = is64;
}

__device__ __forceinline__ void load_edge(const void* __restrict__ ei, int e,
                                          int& s, int& d) {
    if (g_is64) {
        const long long* p = (const long long*)ei;
        s = (int)p[e];
        d = (int)p[EE + e];
    } else {
        const int* p = (const int*)ei;
        s = p[e];
        d = p[EE + e];
    }
}

// ---------------- preprocessing ---------------------------------------------
__global__ void k_zero_pre() {
    int i = blockIdx.x * blockDim.x + threadIdx.x;
    if (i < NN) { g_outdeg[i] = 0; g_indeg[i] = 0; g_cursor[i] = 0; }
}

__global__ void k_hist(const void* __restrict__ ei) {
    int e = blockIdx.x * blockDim.x + threadIdx.x;
    if (e < EE) {
        int s, d;
        load_edge(ei, e, s, d);
        atomicAdd(&g_outdeg[s], 1);
        atomicAdd(&g_indeg[d], 1);
    }
}

__global__ void k_dinv() {
    int i = blockIdx.x * blockDim.x + threadIdx.x;
    if (i < NN) {
        int d = g_outdeg[i];
        g_dinv[i] = (d > 0) ? rsqrtf((float)d) : 0.0f;
    }
}

__global__ void k_scan1() {
    __shared__ int sm[1024];
    int t = threadIdx.x;
    int i = blockIdx.x * 1024 + t;
    int v = (i < NN) ? g_indeg[i] : 0;
    sm[t] = v;
    __syncthreads();
    for (int off = 1; off < 1024; off <<= 1) {
        int x = (t >= off) ? sm[t - off] : 0;
        __syncthreads();
        sm[t] += x;
        __syncthreads();
    }
    if (i < NN) g_rowptr[i] = sm[t] - v;
    if (t == 1023) g_blocksums[blockIdx.x] = sm[t];
}

__global__ void k_scan2() {
    __shared__ int sm[512];
    int t = threadIdx.x;
    int v = (t < NB_SCAN) ? g_blocksums[t] : 0;
    sm[t] = v;
    __syncthreads();
    for (int off = 1; off < 512; off <<= 1) {
        int x = (t >= off) ? sm[t - off] : 0;
        __syncthreads();
        sm[t] += x;
        __syncthreads();
    }
    if (t < NB_SCAN) g_blockoff[t] = sm[t] - v;
}

__global__ void k_scan3() {
    int i = blockIdx.x * blockDim.x + threadIdx.x;
    if (i < NN) g_rowptr[i] += g_blockoff[i >> 10];
    if (i == 0) g_rowptr[NN] = EE;
}

__global__ void k_scatter(const void* __restrict__ ei) {
    int e = blockIdx.x * blockDim.x + threadIdx.x;
    if (e < EE) {
        int s, d;
        load_edge(ei, e, s, d);
        int pos = g_rowptr[d] + atomicAdd(&g_cursor[d], 1);
        g_csrsrc[pos] = s;
        g_csrw[pos]   = -g_dinv[s] * g_dinv[d];
    }
}

// ---------------- layer-0 propagation (width 2) ------------------------------
__global__ void k_prop2(const float* __restrict__ in, const float* __restrict__ sub,
                        float* __restrict__ out, float alpha, float beta) {
    int i = blockIdx.x * blockDim.x + threadIdx.x;
    if (i >= NN) return;
    int p0 = g_rowptr[i], p1 = g_rowptr[i + 1];
    float a0 = 0.f, a1 = 0.f;
    for (int p = p0; p < p1; p++) {
        int s = g_csrsrc[p];
        float w = g_csrw[p];
        a0 += w * in[2 * s];
        a1 += w * in[2 * s + 1];
    }
    if (beta != 0.f) {
        out[2 * i]     = alpha * a0 + beta * sub[2 * i];
        out[2 * i + 1] = alpha * a1 + beta * sub[2 * i + 1];
    } else {
        out[2 * i]     = alpha * a0;
        out[2 * i + 1] = alpha * a1;
    }
}

// ---------------- layer-0 GEMM: [N,2]x5 -> [N,100], +bias, relu --------------
__global__ void k_gemm0(const float* __restrict__ x,  const float* __restrict__ s1,
                        const float* __restrict__ s2, const float* __restrict__ s3,
                        const float* __restrict__ s4, const float* __restrict__ W0,
                        const float* __restrict__ b0, float* __restrict__ Z) {
    __shared__ float sw[1000];
    __shared__ float sb[HH];
    int tid = threadIdx.y * 32 + threadIdx.x;
    for (int i = tid; i < 1000; i += 256) sw[i] = W0[i];
    for (int i = tid; i < HH; i += 256) sb[i] = b0[i];
    __syncthreads();

    int n = blockIdx.x * 8 + threadIdx.y;
    float v[10];
    v[0] = x[2 * n]; v[1] = x[2 * n + 1];
    v[2] = s1[2 * n]; v[3] = s1[2 * n + 1];
    v[4] = s2[2 * n]; v[5] = s2[2 * n + 1];
    v[6] = s3[2 * n]; v[7] = s3[2 * n + 1];
    v[8] = s4[2 * n]; v[9] = s4[2 * n + 1];

    #pragma unroll
    for (int j = 0; j < 4; j++) {
        int c = threadIdx.x + 32 * j;
        if (c < HH) {
            float acc = sb[c];
            #pragma unroll
            for (int k = 0; k < 5; k++) {
                acc += v[2 * k]     * sw[(2 * k) * HH + c];
                acc += v[2 * k + 1] * sw[(2 * k + 1) * HH + c];
            }
            Z[n * HH + c] = fmaxf(acc, 0.0f);
        }
    }
}

// ---------------- width-100 propagation: warp per dst row --------------------
__global__ void __launch_bounds__(256) k_prop100(
    const float* __restrict__ in, const float* __restrict__ sub,
    float* __restrict__ out, float alpha, float beta) {
    int warp = (blockIdx.x * blockDim.x + threadIdx.x) >> 5;
    int lane = threadIdx.x & 31;
    if (warp >= NN) return;
    int p0 = g_rowptr[warp], p1 = g_rowptr[warp + 1];
    float a0 = 0.f, a1 = 0.f, a2 = 0.f, a3 = 0.f;
    for (int p = p0; p < p1; p++) {
        int s = g_csrsrc[p];
        float w = g_csrw[p];
        const float* r = in + (size_t)s * HH;
        a0 += w * r[lane];
        a1 += w * r[lane + 32];
        a2 += w * r[lane + 64];
        if (lane < 4) a3 += w * r[lane + 96];
    }
    float* o = out + (size_t)warp * HH;
    if (beta != 0.f) {
        const float* sb = sub + (size_t)warp * HH;
        o[lane]      = alpha * a0 + beta * sb[lane];
        o[lane + 32] = alpha * a1 + beta * sb[lane + 32];
        o[lane + 64] = alpha * a2 + beta * sb[lane + 64];
        if (lane < 4) o[lane + 96] = alpha * a3 + beta * sb[lane + 96];
    } else {
        o[lane]      = alpha * a0;
        o[lane + 32] = alpha * a1;
        o[lane + 64] = alpha * a2;
        if (lane < 4) o[lane + 96] = alpha * a3;
    }
}

// ---------------- HMMA GEMM: Z = relu([T0..T4]@Wcat + b) ---------------------
// Split-bf16 (A=Ahi+Alo, W=Whi+Wlo; D = Ahi·Whi + Alo·Whi + Ahi·Wlo),
// mma.sync.m16n8k16 bf16 (plain sm_103 — no 'a' features).
// CTA: 128 rows x 128 cols (100 valid), 8 warps as 2(M)x4(N) -> 64x32/warp.
// K: 10 chunks of 64 (5 buffers x pad(100->128)).
// Smem: [row][k] and [n][k], k-contiguous, stride 68 bf16 (=136B, 8B-aligned,
// bank shift 2/row -> conflict-free A-frag loads).
#define SK 34                       // 32-bit words per row (68 bf16)
#define SM_WORDS (128 * SK)         // 4352 words per array
#define SMEM_MMA_BYTES (4 * SM_WORDS * 4)   // 69632

__device__ __forceinline__ void mma_bf16(float* c, const uint32_t* a,
                                         const uint32_t* b) {
    asm volatile(
        "mma.sync.aligned.m16n8k16.row.col.f32.bf16.bf16.f32 "
        "{%0,%1,%2,%3}, {%4,%5,%6,%7}, {%8,%9}, {%0,%1,%2,%3};"
        : "+f"(c[0]), "+f"(c[1]), "+f"(c[2]), "+f"(c[3])
        : "r"(a[0]), "r"(a[1]), "r"(a[2]), "r"(a[3]), "r"(b[0]), "r"(b[1]));
}

__global__ void __launch_bounds__(256) k_gemm_mma(
    const float* __restrict__ t0, const float* __restrict__ t1,
    const float* __restrict__ t2, const float* __restrict__ t3,
    const float* __restrict__ t4,
    const float* __restrict__ W, const float* __restrict__ bias,
    float* __restrict__ Z) {
    extern __shared__ uint32_t smw[];
    uint32_t* sAhi = smw;
    uint32_t* sAlo = smw + SM_WORDS;
    uint32_t* sBhi = smw + 2 * SM_WORDS;
    uint32_t* sBlo = smw + 3 * SM_WORDS;

    int tid = threadIdx.x;
    int wid = tid >> 5, lane = tid & 31;
    int g = lane >> 2, tg = lane & 3;
    int rowbase = blockIdx.x * 128;
    const float* bufs[5] = { t0, t1, t2, t3, t4 };
    int mbase0 = (wid & 1) * 64;        // M: 2 warps
    int nbase0 = (wid >> 1) * 32;       // N: 4 warps

    float acc[4][4][4];
    #pragma unroll
    for (int i = 0; i < 4; i++)
        #pragma unroll
        for (int j = 0; j < 4; j++)
            #pragma unroll
            for (int q = 0; q < 4; q++) acc[i][j][q] = 0.f;

    for (int ch = 0; ch < 10; ch++) {
        int buf = ch >> 1;
        int col0 = (ch & 1) * 64;
        int nvalid = HH - col0;          // 100 or 36 (both mult of 4)
        __syncthreads();                 // prior chunk's compute done

        // ---- stage A: 128 rows x 64 k, fp32 -> split bf16 ----
        const float* A = bufs[buf];
        #pragma unroll
        for (int it = 0; it < 8; it++) {
            int slot = tid + it * 256;           // 0..2047
            int r  = slot >> 4;
            int c4 = (slot & 15) << 2;           // 0..60
            float4 v = make_float4(0.f, 0.f, 0.f, 0.f);
            if (c4 < nvalid)
                v = *(const float4*)(A + (size_t)(rowbase + r) * HH + col0 + c4);
            __nv_bfloat162 h01 = __floats2bfloat162_rn(v.x, v.y);
            __nv_bfloat162 h23 = __floats2bfloat162_rn(v.z, v.w);
            __nv_bfloat162 l01 = __floats2bfloat162_rn(
                v.x - __bfloat162float(h01.x), v.y - __bfloat162float(h01.y));
            __nv_bfloat162 l23 = __floats2bfloat162_rn(
                v.z - __bfloat162float(h23.x), v.w - __bfloat162float(h23.y));
            int w = r * SK + (c4 >> 1);
            sAhi[w] = *(uint32_t*)&h01; sAhi[w + 1] = *(uint32_t*)&h23;
            sAlo[w] = *(uint32_t*)&l01; sAlo[w + 1] = *(uint32_t*)&l23;
        }
        // ---- stage B: W[k][n] -> smem [n][k], split bf16, pad n&k ----
        const float* Wc = W + (size_t)(buf * HH + col0) * HH;
        #pragma unroll
        for (int it = 0; it < 16; it++) {
            int slot = tid + it * 256;           // 0..4095
            int n  = slot >> 5;                  // 0..127
            int k2 = (slot & 31) << 1;           // 0..62
            float w0 = 0.f, w1 = 0.f;
            if (n < HH) {
                if (k2     < nvalid) w0 = Wc[(size_t)k2 * HH + n];
                if (k2 + 1 < nvalid) w1 = Wc[(size_t)(k2 + 1) * HH + n];
            }
            __nv_bfloat162 h = __floats2bfloat162_rn(w0, w1);
            __nv_bfloat162 l = __floats2bfloat162_rn(
                w0 - __bfloat162float(h.x), w1 - __bfloat162float(h.y));
            int w = n * SK + (k2 >> 1);
            sBhi[w] = *(uint32_t*)&h;
            sBlo[w] = *(uint32_t*)&l;
        }
        __syncthreads();

        // ---- 4 K16 steps ----
        #pragma unroll
        for (int st = 0; st < 4; st++) {
            int kw = st * 8;
            uint32_t Ah[4][4], Al[4][4];
            #pragma unroll
            for (int i = 0; i < 4; i++) {
                int r0 = (mbase0 + i * 16 + g) * SK + kw + tg;
                int r8 = r0 + 8 * SK;
                Ah[i][0] = sAhi[r0];     Ah[i][1] = sAhi[r8];
                Ah[i][2] = sAhi[r0 + 4]; Ah[i][3] = sAhi[r8 + 4];
                Al[i][0] = sAlo[r0];     Al[i][1] = sAlo[r8];
                Al[i][2] = sAlo[r0 + 4]; Al[i][3] = sAlo[r8 + 4];
            }
            uint32_t Bh[4][2], Bl[4][2];
            #pragma unroll
            for (int j = 0; j < 4; j++) {
                int n0 = (nbase0 + j * 8 + g) * SK + kw + tg;
                Bh[j][0] = sBhi[n0]; Bh[j][1] = sBhi[n0 + 4];
                Bl[j][0] = sBlo[n0]; Bl[j][1] = sBlo[n0 + 4];
            }
            #pragma unroll
            for (int i = 0; i < 4; i++)
                #pragma unroll
                for (int j = 0; j < 4; j++) {
                    mma_bf16(acc[i][j], Ah[i], Bh[j]);
                    mma_bf16(acc[i][j], Al[i], Bh[j]);
                    mma_bf16(acc[i][j], Ah[i], Bl[j]);
                }
        }
    }

    // ---- epilogue: bias + relu + store (cols >= 100 dropped) ----
    #pragma unroll
    for (int j = 0; j < 4; j++) {
        int col = nbase0 + j * 8 + tg * 2;
        if (col >= HH) continue;
        float b0v = bias[col], b1v = bias[col + 1];
        #pragma unroll
        for (int i = 0; i < 4; i++) {
            int row = rowbase + mbase0 + i * 16 + g;
            float2 v0, v1;
            v0.x = fmaxf(acc[i][j][0] + b0v, 0.f);
            v0.y = fmaxf(acc[i][j][1] + b1v, 0.f);
            v1.x = fmaxf(acc[i][j][2] + b0v, 0.f);
            v1.y = fmaxf(acc[i][j][3] + b1v, 0.f);
            *(float2*)(Z + (size_t)row * HH + col)       = v0;
            *(float2*)(Z + (size_t)(row + 8) * HH + col) = v1;
        }
    }
}

// ---------------- batch-norm ------------------------------------------------
__global__ void k_zero_bn() {
    int i = threadIdx.x;
    if (i < HH) { g_colsum[i] = 0.f; g_colsq[i] = 0.f; }
}

__global__ void k_stats(const float* __restrict__ Z) {
    int tx = threadIdx.x, ty = threadIdx.y;
    int r0 = blockIdx.x * 1000;
    float s[4] = {0, 0, 0, 0}, q[4] = {0, 0, 0, 0};
    for (int r = r0 + ty; r < r0 + 1000; r += 8) {
        const float* zr = Z + (size_t)r * HH;
        #pragma unroll
        for (int j = 0; j < 4; j++) {
            int c = tx + 32 * j;
            if (c < HH) {
                float v = zr[c];
                s[j] += v;
                q[j] += v * v;
            }
        }
    }
    #pragma unroll
    for (int j = 0; j < 4; j++) {
        int c = tx + 32 * j;
        if (c < HH) {
            atomicAdd(&g_colsum[c], s[j]);
            atomicAdd(&g_colsq[c], q[j]);
        }
    }
}

__global__ void k_bnfinal(const float* __restrict__ gamma, const float* __restrict__ beta) {
    int c = threadIdx.x;
    if (c < HH) {
        float m = g_colsum[c] * (1.0f / NN);
        float v = g_colsq[c] * (1.0f / NN) - m * m;
        float a = gamma[c] * rsqrtf(v + 1e-5f);
        g_bna[c] = a;
        g_bnb[c] = beta[c] - a * m;
    }
}

__global__ void k_norm(const float* __restrict__ Z, float* __restrict__ out) {
    int i = blockIdx.x * blockDim.x + threadIdx.x;
    if (i >= NN * HH / 4) return;
    float4 z = ((const float4*)Z)[i];
    int c0 = (i % 25) * 4;
    float4 r;
    r.x = g_bna[c0]     * z.x + g_bnb[c0];
    r.y = g_bna[c0 + 1] * z.y + g_bnb[c0 + 1];
    r.z = g_bna[c0 + 2] * z.z + g_bnb[c0 + 2];
    r.w = g_bna[c0 + 3] * z.w + g_bnb[c0 + 3];
    ((float4*)out)[i] = r;
}

// ---------------- host ------------------------------------------------------
extern "C" void kernel_launch(void* const* d_in, const int* in_sizes, int n_in,
                              void* d_out, int out_size) {
    const float* x     = (const float*)d_in[0];
    const void*  ei    = d_in[1];          // int32 or int64 — detected on device
    const float* W0    = (const float*)d_in[2];
    const float* b0    = (const float*)d_in[3];
    const float* Wr    = (const float*)d_in[4];
    const float* br    = (const float*)d_in[5];
    const float* gamma = (const float*)d_in[6];
    const float* beta  = (const float*)d_in[7];
    float* out = (float*)d_out;

    float *h, *t1, *t2, *t3, *t4, *z, *s1, *s2, *s3, *s4;
    cudaGetSymbolAddress((void**)&h,  g_h);
    cudaGetSymbolAddress((void**)&t1, g_t1);
    cudaGetSymbolAddress((void**)&t2, g_t2);
    cudaGetSymbolAddress((void**)&t3, g_t3);
    cudaGetSymbolAddress((void**)&t4, g_t4);
    cudaGetSymbolAddress((void**)&z,  g_z);
    cudaGetSymbolAddress((void**)&s1, g_s1);
    cudaGetSymbolAddress((void**)&s2, g_s2);
    cudaGetSymbolAddress((void**)&s3, g_s3);
    cudaGetSymbolAddress((void**)&s4, g_s4);

    cudaFuncSetAttribute(k_gemm_mma, cudaFuncAttributeMaxDynamicSharedMemorySize,
                         SMEM_MMA_BYTES);

    const int TB = 256;
    const int gN = (NN + TB - 1) / TB;   // 1563
    const int gE = (EE + TB - 1) / TB;   // 12500

    // ---- CSR preprocessing (dst-sorted, atomic-free props afterwards) ----
    k_detect<<<1, 1>>>(ei);
    k_zero_pre<<<gN, TB>>>();
    k_hist<<<gE, TB>>>(ei);
    k_dinv<<<gN, TB>>>();
    k_scan1<<<NB_SCAN, 1024>>>();
    k_scan2<<<1, 512>>>();
    k_scan3<<<gN, TB>>>();
    k_scatter<<<gE, TB>>>(ei);

    // ---- layer 0 (width F_IN=2) ----
    k_prop2<<<gN, TB>>>(x,  x,  s1, 1.f,  0.f);
    k_prop2<<<gN, TB>>>(s1, x,  s2, 2.f, -1.f);
    k_prop2<<<gN, TB>>>(s2, s1, s3, 2.f, -1.f);
    k_prop2<<<gN, TB>>>(s3, s2, s4, 2.f, -1.f);
    k_gemm0<<<NN / 8, dim3(32, 8)>>>(x, s1, s2, s3, s4, W0, b0, z);
    k_zero_bn<<<1, 128>>>();
    k_stats<<<400, dim3(32, 8)>>>(z);
    k_bnfinal<<<1, 128>>>(gamma, beta);
    k_norm<<<(NN * HH / 4 + TB - 1) / TB, TB>>>(z, h);

    // ---- layers 1..4 (width 100) ----
    for (int l = 1; l < 5; l++) {
        k_prop100<<<NN / 8, TB>>>(h,  h,  t1, 1.f,  0.f);
        k_prop100<<<NN / 8, TB>>>(t1, h,  t2, 2.f, -1.f);
        k_prop100<<<NN / 8, TB>>>(t2, t1, t3, 2.f, -1.f);
        k_prop100<<<NN / 8, TB>>>(t3, t2, t4, 2.f, -1.f);
        k_gemm_mma<<<NN / 128, 256, SMEM_MMA_BYTES>>>(
            h, t1, t2, t3, t4,
            Wr + (size_t)(l - 1) * 5 * HH * HH, br + (l - 1) * HH, z);
        k_zero_bn<<<1, 128>>>();
        k_stats<<<400, dim3(32, 8)>>>(z);
        k_bnfinal<<<1, 128>>>(gamma + l * HH, beta + l * HH);
        k_norm<<<(NN * HH / 4 + TB - 1) / TB, TB>>>(z, (l == 4) ? out : h);
    }
}